// round 1
// baseline (speedup 1.0000x reference)
#include <cuda_runtime.h>

#define PAIRS 80
#define SEQ   2048
#define VD    768
#define HID   512
#define HID2  1024
#define NOUT  5
#define NCHUNK 16
#define ROWS_PER_CHUNK (SEQ / NCHUNK)   // 128

// ---------------- scratch (static device globals; no allocs) ----------------
__device__ float g_X[PAIRS * HID2];     // concat buffer: [:,0:512]=pooled_v, [:,512:1024]=q
__device__ float g_QQ[PAIRS * HID2];
__device__ float g_WKQ[PAIRS * HID];
__device__ float g_U[PAIRS * VD];
__device__ float g_R[PAIRS * VD];
__device__ float g_PH[PAIRS * HID];
__device__ float g_H[PAIRS * HID];
__device__ float g_Pacc[PAIRS * NCHUNK * VD];
__device__ float g_Pm[PAIRS * NCHUNK];
__device__ float g_Pl[PAIRS * NCHUNK];

// ---------------- init: bias-initialize split-K atomic outputs ----------------
__global__ void init_kernel(const float* __restrict__ bqp,
                            const float* __restrict__ bvp,
                            const float* __restrict__ b1) {
    int t = blockIdx.x * blockDim.x + threadIdx.x;
    if (t < PAIRS * HID2) {
        int col = t & (HID2 - 1);
        g_X[t]  = (col < HID) ? 0.f : bqp[col - HID];
        g_QQ[t] = 0.f;
    }
    if (t < PAIRS * HID) {
        int col = t & (HID - 1);
        g_WKQ[t] = 0.f;
        g_PH[t]  = bvp[col];
        g_H[t]   = b1[col];
    }
    if (t < PAIRS * VD) g_U[t] = 0.f;
}

// ---------------- generic skinny GEMM: out[p][r] (+)= scale * sum_k in[p][k]*W(k,r) ----
// NT: W row-major [R, C], dot along contiguous C.   TN: W [C, R], sum over row index.
// Tile: 16 pairs x 64 rows, K-step 64, 128 threads, split-K via blockIdx.z + atomicAdd.
template <bool TN>
__global__ __launch_bounds__(128)
void gemm_splitk(const float* __restrict__ in, int in_ld,
                 const float* __restrict__ W, int wld,
                 float* __restrict__ out, int out_ld,
                 int kchunk, float scale) {
    __shared__ float As[16][68];                 // pad 68: conflict-free a-reads, 16B-aligned f4 stores
    __shared__ float Bs[64][TN ? 64 : 65];       // TN: [k][r] (f4 reads); NT: [r][k] pad 65

    const int tx = threadIdx.x;
    const int ty = tx >> 4;        // 0..7
    const int tc = tx & 15;        // 0..15
    const int r0 = blockIdx.x * 64;
    const int p0 = blockIdx.y * 16;
    const int kbase = blockIdx.z * kchunk;

    float acc[2][4] = {{0.f, 0.f, 0.f, 0.f}, {0.f, 0.f, 0.f, 0.f}};

    for (int ks = 0; ks < kchunk; ks += 64) {
        const int k0 = kbase + ks;
#pragma unroll
        for (int i = 0; i < 2; i++) {           // As: 16x64
            int f = tx + 128 * i;
            int p = f >> 4, kq = f & 15;
            float4 v = *(const float4*)(in + (size_t)(p0 + p) * in_ld + k0 + 4 * kq);
            *(float4*)&As[p][4 * kq] = v;
        }
#pragma unroll
        for (int i = 0; i < 8; i++) {           // Bs: 64x64
            int f = tx + 128 * i;
            if (TN) {
                int k = f >> 4, rq = f & 15;
                float4 v = *(const float4*)(W + (size_t)(k0 + k) * wld + r0 + 4 * rq);
                *(float4*)&Bs[k][4 * rq] = v;
            } else {
                int r = f >> 4, kq = f & 15;
                float4 v = *(const float4*)(W + (size_t)(r0 + r) * wld + k0 + 4 * kq);
                Bs[r][4 * kq + 0] = v.x; Bs[r][4 * kq + 1] = v.y;
                Bs[r][4 * kq + 2] = v.z; Bs[r][4 * kq + 3] = v.w;
            }
        }
        __syncthreads();
#pragma unroll 16
        for (int kk = 0; kk < 64; kk++) {
            float a0 = As[2 * ty + 0][kk];
            float a1 = As[2 * ty + 1][kk];
            float b0, b1, b2, b3;
            if (TN) {
                float4 b = *(const float4*)&Bs[kk][4 * tc];
                b0 = b.x; b1 = b.y; b2 = b.z; b3 = b.w;
            } else {
                b0 = Bs[4 * tc + 0][kk]; b1 = Bs[4 * tc + 1][kk];
                b2 = Bs[4 * tc + 2][kk]; b3 = Bs[4 * tc + 3][kk];
            }
            acc[0][0] += a0 * b0; acc[0][1] += a0 * b1; acc[0][2] += a0 * b2; acc[0][3] += a0 * b3;
            acc[1][0] += a1 * b0; acc[1][1] += a1 * b1; acc[1][2] += a1 * b2; acc[1][3] += a1 * b3;
        }
        __syncthreads();
    }
#pragma unroll
    for (int pp = 0; pp < 2; pp++)
#pragma unroll
        for (int jj = 0; jj < 4; jj++)
            atomicAdd(&out[(size_t)(p0 + 2 * ty + pp) * out_ld + r0 + 4 * tc + jj],
                      acc[pp][jj] * scale);
}

// ---------------- flash: scores + online-softmax pooled accumulation ----------------
// grid = (NCHUNK, PAIRS), 256 threads (8 warps). Warp handles rows w, w+8, ...
__global__ __launch_bounds__(256)
void flash_kernel(const float* __restrict__ video) {
    const int chunk = blockIdx.x;
    const int pair  = blockIdx.y;
    const int w = threadIdx.x >> 5, lane = threadIdx.x & 31;

    const float4* u4 = (const float4*)(g_U + (size_t)pair * VD);
    float4 uv[6];
#pragma unroll
    for (int j = 0; j < 6; j++) uv[j] = u4[lane + 32 * j];

    float m = -1e30f, l = 0.f;
    float4 acc[6];
#pragma unroll
    for (int j = 0; j < 6; j++) acc[j] = make_float4(0.f, 0.f, 0.f, 0.f);

    const float* base = video + ((size_t)pair * SEQ + (size_t)chunk * ROWS_PER_CHUNK) * VD;

    for (int r = w; r < ROWS_PER_CHUNK; r += 8) {
        const float4* x4 = (const float4*)(base + (size_t)r * VD);
        float4 xv[6];
#pragma unroll
        for (int j = 0; j < 6; j++) xv[j] = x4[lane + 32 * j];
        float s = 0.f;
#pragma unroll
        for (int j = 0; j < 6; j++)
            s += xv[j].x * uv[j].x + xv[j].y * uv[j].y + xv[j].z * uv[j].z + xv[j].w * uv[j].w;
#pragma unroll
        for (int o = 16; o > 0; o >>= 1) s += __shfl_xor_sync(0xffffffffu, s, o);

        float mn   = fmaxf(m, s);
        float corr = __expf(m - mn);
        float p    = __expf(s - mn);
        l = l * corr + p;
#pragma unroll
        for (int j = 0; j < 6; j++) {
            acc[j].x = acc[j].x * corr + p * xv[j].x;
            acc[j].y = acc[j].y * corr + p * xv[j].y;
            acc[j].z = acc[j].z * corr + p * xv[j].z;
            acc[j].w = acc[j].w * corr + p * xv[j].w;
        }
        m = mn;
    }

    __shared__ float sm[8], sl[8];
    __shared__ float sacc[8][VD];
    if (lane == 0) { sm[w] = m; sl[w] = l; }
    float4* sa4 = (float4*)sacc[w];
#pragma unroll
    for (int j = 0; j < 6; j++) sa4[lane + 32 * j] = acc[j];
    __syncthreads();

    float M = sm[0];
#pragma unroll
    for (int i = 1; i < 8; i++) M = fmaxf(M, sm[i]);
    float wsc[8], L = 0.f;
#pragma unroll
    for (int i = 0; i < 8; i++) { wsc[i] = __expf(sm[i] - M); L += wsc[i] * sl[i]; }

    const int t = threadIdx.x;
    for (int d = t; d < VD; d += 256) {
        float a = 0.f;
#pragma unroll
        for (int i = 0; i < 8; i++) a += wsc[i] * sacc[i][d];
        g_Pacc[((size_t)pair * NCHUNK + chunk) * VD + d] = a;
    }
    if (t == 0) { g_Pm[pair * NCHUNK + chunk] = M; g_Pl[pair * NCHUNK + chunk] = L; }
}

// ---------------- combine split-S partials -> r = attn^T @ video ----------------
__global__ __launch_bounds__(256)
void combine_kernel() {
    const int pair = blockIdx.x, t = threadIdx.x;
    __shared__ float wsc[NCHUNK];
    __shared__ float sInvL;
    if (t == 0) {
        float M = g_Pm[pair * NCHUNK];
        for (int c = 1; c < NCHUNK; c++) M = fmaxf(M, g_Pm[pair * NCHUNK + c]);
        float L = 0.f;
        for (int c = 0; c < NCHUNK; c++) {
            float e = __expf(g_Pm[pair * NCHUNK + c] - M);
            wsc[c] = e;
            L += e * g_Pl[pair * NCHUNK + c];
        }
        sInvL = 1.f / L;
    }
    __syncthreads();
    const float invL = sInvL;
    for (int d = t; d < VD; d += 256) {
        float a = 0.f;
#pragma unroll
        for (int c = 0; c < NCHUNK; c++)
            a += wsc[c] * g_Pacc[((size_t)pair * NCHUNK + c) * VD + d];
        g_R[(size_t)pair * VD + d] = a * invL;
    }
}

// ---------------- final: out = softmax(relu(h) @ W2^T + b2 + mask) ----------------
__global__ __launch_bounds__(32)
void final_kernel(const float* __restrict__ W2, const float* __restrict__ b2,
                  const float* __restrict__ omask, float* __restrict__ out) {
    const int pair = blockIdx.x, lane = threadIdx.x;
    float o[NOUT] = {0.f, 0.f, 0.f, 0.f, 0.f};
    for (int h = lane; h < HID; h += 32) {
        float hv = fmaxf(g_H[pair * HID + h], 0.f);
#pragma unroll
        for (int j = 0; j < NOUT; j++) o[j] += hv * W2[j * HID + h];
    }
#pragma unroll
    for (int j = 0; j < NOUT; j++)
#pragma unroll
        for (int off = 16; off > 0; off >>= 1)
            o[j] += __shfl_xor_sync(0xffffffffu, o[j], off);
    if (lane == 0) {
        float x[NOUT], mx = -1e30f;
#pragma unroll
        for (int j = 0; j < NOUT; j++) {
            x[j] = o[j] + b2[j] + omask[pair * NOUT + j];
            mx = fmaxf(mx, x[j]);
        }
        float e[NOUT], s = 0.f;
#pragma unroll
        for (int j = 0; j < NOUT; j++) { e[j] = __expf(x[j] - mx); s += e[j]; }
#pragma unroll
        for (int j = 0; j < NOUT; j++) out[pair * NOUT + j] = e[j] / s;
    }
}

// ---------------- launch ----------------
extern "C" void kernel_launch(void* const* d_in, const int* in_sizes, int n_in,
                              void* d_out, int out_size) {
    (void)in_sizes; (void)n_in; (void)out_size;
    const float* video = (const float*)d_in[0];
    const float* ques  = (const float*)d_in[1];
    const float* omask = (const float*)d_in[3];
    const float* Wvp   = (const float*)d_in[4];
    const float* bvp   = (const float*)d_in[5];
    const float* Wqp   = (const float*)d_in[6];
    const float* bqp   = (const float*)d_in[7];
    const float* Wk    = (const float*)d_in[8];
    const float* Wv    = (const float*)d_in[9];
    const float* Wq    = (const float*)d_in[10];
    const float* W1    = (const float*)d_in[11];
    const float* b1    = (const float*)d_in[12];
    const float* W2    = (const float*)d_in[13];
    const float* b2    = (const float*)d_in[14];
    float* out = (float*)d_out;

    float *X, *QQ, *WKQ, *U, *R, *PH, *H;
    cudaGetSymbolAddress((void**)&X,   g_X);
    cudaGetSymbolAddress((void**)&QQ,  g_QQ);
    cudaGetSymbolAddress((void**)&WKQ, g_WKQ);
    cudaGetSymbolAddress((void**)&U,   g_U);
    cudaGetSymbolAddress((void**)&R,   g_R);
    cudaGetSymbolAddress((void**)&PH,  g_PH);
    cudaGetSymbolAddress((void**)&H,   g_H);

    dim3 blk(128);

    // biases into atomic-accumulated outputs
    init_kernel<<<(PAIRS * HID2 + 255) / 256, 256>>>(bqp, bvp, b1);
    // q = ques[:,:,0,:] @ Wqp^T + bqp  -> X[:,512:]
    gemm_splitk<false><<<dim3(HID / 64, 5, 4), blk>>>(ques, 32 * VD, Wqp, VD, X + HID, HID2, VD / 4, 1.f);
    // qq = q @ Wq^T
    gemm_splitk<false><<<dim3(HID2 / 64, 5, 2), blk>>>(X + HID, HID2, Wq, HID, QQ, HID2, HID / 2, 1.f);
    // wkq = Wk^T @ qq   (sum over Wk row index)
    gemm_splitk<true ><<<dim3(HID / 64, 5, 4), blk>>>(QQ, HID2, Wk, HID, WKQ, HID, HID2 / 4, 1.f);
    // u = Wvp^T @ wkq / sqrt(2H)
    gemm_splitk<true ><<<dim3(VD / 64, 5, 2), blk>>>(WKQ, HID, Wvp, VD, U, VD, HID / 2, 1.f / 32.f);
    // flash: scores + online softmax pooled accumulation over video_enc (single HBM pass)
    flash_kernel<<<dim3(NCHUNK, PAIRS), 256>>>(video);
    combine_kernel<<<PAIRS, 256>>>();
    // pooled_h = r @ Wvp^T + bvp
    gemm_splitk<false><<<dim3(HID / 64, 5, 4), blk>>>(R, VD, Wvp, VD, PH, HID, VD / 4, 1.f);
    // pooled_v = pooled_h @ Wv^T -> X[:, :512]
    gemm_splitk<false><<<dim3(HID / 64, 5, 4), blk>>>(PH, HID, Wv, HID, X, HID2, HID / 4, 1.f);
    // h = X @ W1^T + b1 (relu deferred to final)
    gemm_splitk<false><<<dim3(HID / 64, 5, 4), blk>>>(X, HID2, W1, HID2, H, HID, HID2 / 4, 1.f);
    // out = softmax(relu(h) @ W2^T + b2 + output_mask)
    final_kernel<<<PAIRS, 32>>>(W2, b2, omask, out);
}